// round 5
// baseline (speedup 1.0000x reference)
#include <cuda_runtime.h>
#include <cuda_bf16.h>
#include <math.h>
#include <stdint.h>

// Problem constants
#define S_LEN 2048
#define BATCH 2
#define DMODEL 512
#define NHEAD 8
#define HDIM 64
#define FFDIM 2048
#define NTOK (S_LEN * BATCH)   // 4096
#define WWIN 5
#define LN_EPS 1e-5f

// ---------------- scratch (no allocations allowed) ----------------
__device__ float g_qkv[(size_t)NTOK * 3 * DMODEL];   // [tok, q|k|v] 24 MB
__device__ float g_attn[(size_t)NTOK * DMODEL];      // rounded tf32
__device__ float g_tmp[(size_t)NTOK * DMODEL];
__device__ float g_x1[(size_t)NTOK * DMODEL];
__device__ float g_x2[(size_t)NTOK * DMODEL];
__device__ float g_ff[(size_t)NTOK * FFDIM];         // rounded tf32 (epilogue)
__device__ float g_kv[(size_t)NTOK * 2 * DMODEL];    // cross K|V
__device__ float g_qc[(size_t)NTOK * DMODEL];        // cross Q
// rounded tf32 copies for MMA inputs
__device__ float g_wr[4194304];
__device__ float g_xr[(size_t)NTOK * DMODEL];
__device__ float g_encr[(size_t)NTOK * DMODEL];
__device__ float g_x1r[(size_t)NTOK * DMODEL];
__device__ float g_x2r[(size_t)NTOK * DMODEL];
// concatenated biases
__device__ float g_bsa[3 * DMODEL];
__device__ float g_bca[2 * DMODEL];

// epilogue flags
#define EF_RELU    1
#define EF_RES     4
#define EF_ROUND   8

__device__ __forceinline__ float tf32_rna(float x) {
    uint32_t u;
    asm("cvt.rna.tf32.f32 %0, %1;" : "=r"(u) : "f"(x));
    return __uint_as_float(u);
}

// ---------------- copy/round kernel ----------------
#define NCVT 17
struct CvtArgs {
    const float* src[NCVT];
    float* dst[NCVT];
    int n4[NCVT];
    int rnd[NCVT];
};

__global__ __launch_bounds__(256) void cvt_kernel(CvtArgs args) {
    const int ti = blockIdx.y;
    const int n4 = args.n4[ti];
    const int rnd = args.rnd[ti];
    const float4* src = (const float4*)args.src[ti];
    float4* dst = (float4*)args.dst[ti];
    for (int i = blockIdx.x * 256 + threadIdx.x; i < n4; i += gridDim.x * 256) {
        float4 v = src[i];
        if (rnd) {
            v.x = tf32_rna(v.x); v.y = tf32_rna(v.y);
            v.z = tf32_rna(v.z); v.w = tf32_rna(v.w);
        }
        dst[i] = v;
    }
}

// ---------------- tf32 tensor-core GEMM ----------------
// C[m,n] = sum_k A[m,k]*Bw[n,k] + bias[n].  BM=BN=64, BK=32, 128 threads (4 warps).
// Warp tile 32x32 (2 m-frags x 4 n-frags of m16n8k8).
#define GBM 64
#define GBN 64
#define GBK 32
#define APAD 36
#define STAGE (64 * APAD)
#define GEMM_SMEM_BYTES (4 * STAGE * 4)   // 36864

__device__ __forceinline__ void cp16(void* dst, const void* src) {
    uint32_t d = (uint32_t)__cvta_generic_to_shared(dst);
    asm volatile("cp.async.cg.shared.global [%0], [%1], 16;" :: "r"(d), "l"(src));
}

__device__ __forceinline__ void mma_tf32(float* d, const uint32_t* a, const uint32_t* b) {
    asm volatile(
        "mma.sync.aligned.m16n8k8.row.col.f32.tf32.tf32.f32 "
        "{%0,%1,%2,%3},{%4,%5,%6,%7},{%8,%9},{%0,%1,%2,%3};"
        : "+f"(d[0]), "+f"(d[1]), "+f"(d[2]), "+f"(d[3])
        : "r"(a[0]), "r"(a[1]), "r"(a[2]), "r"(a[3]), "r"(b[0]), "r"(b[1]));
}

__global__ __launch_bounds__(128, 6) void gemm_tf32_kernel(
    const float* __restrict__ A, const float* __restrict__ Bw,
    const float* __restrict__ bias, const float* __restrict__ res,
    float* __restrict__ C, int M, int N, int K, int flags)
{
    extern __shared__ float smem[];
    float* As[2] = { smem, smem + STAGE };
    float* Bs[2] = { smem + 2 * STAGE, smem + 3 * STAGE };

    const int t = threadIdx.x;
    const int lane = t & 31;
    const int warp = t >> 5;
    const int wm = warp >> 1;        // 0..1
    const int wn = warp & 1;         // 0..1
    const int r = lane >> 2;         // 0..7
    const int c = lane & 3;          // 0..3

    const int bm = blockIdx.y * GBM;
    const int bn = blockIdx.x * GBN;

    // load mapping: 64 rows x 32 floats; 2 threads/row, 4 float4 each
    const int lrow = t >> 1;                // 0..63
    const int lq = (t & 1) * 4;             // float4 base index 0 or 4

    const float* Abase = A + (size_t)(bm + lrow) * K + lq * 4;
    const float* Bbase = Bw + (size_t)(bn + lrow) * K + lq * 4;
    float* AsRow[2] = { As[0] + lrow * APAD + lq * 4, As[1] + lrow * APAD + lq * 4 };
    float* BsRow[2] = { Bs[0] + lrow * APAD + lq * 4, Bs[1] + lrow * APAD + lq * 4 };

    float acc[2][4][4];
#pragma unroll
    for (int i = 0; i < 2; i++)
#pragma unroll
        for (int j = 0; j < 4; j++)
#pragma unroll
            for (int l = 0; l < 4; l++) acc[i][j][l] = 0.f;

    const int TK = K >> 5;

    {
#pragma unroll
        for (int j = 0; j < 4; j++) {
            cp16(AsRow[0] + j * 4, Abase + j * 4);
            cp16(BsRow[0] + j * 4, Bbase + j * 4);
        }
        asm volatile("cp.async.commit_group;");
    }

    const int amb = wm * 32;
    const int bnb = wn * 32;

    for (int kt = 0; kt < TK; kt++) {
        const int cur = kt & 1;
        const int nxt = cur ^ 1;
        if (kt + 1 < TK) {
            const int ko = (kt + 1) * GBK;
#pragma unroll
            for (int j = 0; j < 4; j++) {
                cp16(AsRow[nxt] + j * 4, Abase + ko + j * 4);
                cp16(BsRow[nxt] + j * 4, Bbase + ko + j * 4);
            }
            asm volatile("cp.async.commit_group;");
            asm volatile("cp.async.wait_group 1;");
        } else {
            asm volatile("cp.async.wait_group 0;");
        }
        __syncthreads();

        const float* Ac = As[cur];
        const float* Bc = Bs[cur];

        uint32_t af[2][2][4];   // [buf][mt][4]
        uint32_t bf[2][4][2];   // [buf][nt][2]

        // prefetch ks=0 fragments
#pragma unroll
        for (int mt = 0; mt < 2; mt++) {
            const int mb = amb + mt * 16;
            af[0][mt][0] = __float_as_uint(Ac[(mb + r) * APAD + c]);
            af[0][mt][1] = __float_as_uint(Ac[(mb + r + 8) * APAD + c]);
            af[0][mt][2] = __float_as_uint(Ac[(mb + r) * APAD + c + 4]);
            af[0][mt][3] = __float_as_uint(Ac[(mb + r + 8) * APAD + c + 4]);
        }
#pragma unroll
        for (int nt = 0; nt < 4; nt++) {
            const int nb = bnb + nt * 8;
            bf[0][nt][0] = __float_as_uint(Bc[(nb + r) * APAD + c]);
            bf[0][nt][1] = __float_as_uint(Bc[(nb + r) * APAD + c + 4]);
        }

#pragma unroll
        for (int ks = 0; ks < 4; ks++) {
            const int cb = ks & 1;
            if (ks < 3) {
                const int k0 = (ks + 1) * 8;
                const int nb2 = cb ^ 1;
#pragma unroll
                for (int mt = 0; mt < 2; mt++) {
                    const int mb = amb + mt * 16;
                    af[nb2][mt][0] = __float_as_uint(Ac[(mb + r) * APAD + k0 + c]);
                    af[nb2][mt][1] = __float_as_uint(Ac[(mb + r + 8) * APAD + k0 + c]);
                    af[nb2][mt][2] = __float_as_uint(Ac[(mb + r) * APAD + k0 + c + 4]);
                    af[nb2][mt][3] = __float_as_uint(Ac[(mb + r + 8) * APAD + k0 + c + 4]);
                }
#pragma unroll
                for (int nt = 0; nt < 4; nt++) {
                    const int nb = bnb + nt * 8;
                    bf[nb2][nt][0] = __float_as_uint(Bc[(nb + r) * APAD + k0 + c]);
                    bf[nb2][nt][1] = __float_as_uint(Bc[(nb + r) * APAD + k0 + c + 4]);
                }
            }
#pragma unroll
            for (int mt = 0; mt < 2; mt++)
#pragma unroll
                for (int nt = 0; nt < 4; nt++)
                    mma_tf32(acc[mt][nt], af[cb][mt], bf[cb][nt]);
        }
        __syncthreads();
    }

    // epilogue: plain row-major store
#pragma unroll
    for (int mt = 0; mt < 2; mt++) {
        const int m0 = bm + amb + mt * 16 + r;
#pragma unroll
        for (int nt = 0; nt < 4; nt++) {
            const int n0 = bn + bnb + nt * 8 + c * 2;
#pragma unroll
            for (int e = 0; e < 4; e++) {
                const int m = m0 + (e >> 1) * 8;
                const int n = n0 + (e & 1);
                float v = acc[mt][nt][e] + bias[n];
                if (flags & EF_RELU) v = fmaxf(v, 0.f);
                if (flags & EF_RES)  v += res[(size_t)m * N + n];
                if (flags & EF_ROUND) v = tf32_rna(v);
                C[(size_t)m * N + n] = v;
            }
        }
    }
}

// ---------------- sparse attention, 4 threads per query ----------------
// Token-row layout: row(tok s, batch b) = s*2+b. Head h occupies cols [h*64, h*64+64)
// of its buffer. Q at ldq stride, K/V at ldk stride.
// allowed(j|i) = |j-i| <= 5  OR  j % 10 == 0. fixed-max softmax (scores bounded).
#define AQ_PER_BLOCK 64
#define STRIDED_KEYS 205   // ceil(2048/10)
#define KTILE 32

__global__ __launch_bounds__(256) void attn4_kernel(
    const float* __restrict__ Qb, int ldq,
    const float* __restrict__ Kb, const float* __restrict__ Vb, int ldk,
    float* __restrict__ O)
{
    __shared__ float sK[KTILE * 64];
    __shared__ float sV[KTILE * 64];

    const int t = threadIdx.x;
    const int bh = blockIdx.y;
    const int b = bh >> 3;
    const int h = bh & 7;
    const int hcol = h * HDIM;
    const int qi = blockIdx.x * AQ_PER_BLOCK + (t >> 2);
    const int dimbase = (t & 3) * 16;

    float4 q[4];
    const float4* qp = (const float4*)(Qb + (size_t)(qi * BATCH + b) * ldq + hcol + dimbase);
#pragma unroll
    for (int f = 0; f < 4; f++) q[f] = qp[f];

    float4 acc[4];
#pragma unroll
    for (int f = 0; f < 4; f++) acc[f] = make_float4(0.f, 0.f, 0.f, 0.f);
    float lsum = 0.f;

    // ---- strided keys via smem tiles ----
    for (int cb = 0; cb < STRIDED_KEYS; cb += KTILE) {
        const int cnt = min(KTILE, STRIDED_KEYS - cb);
        __syncthreads();
        for (int idx = t; idx < cnt * 16; idx += 256) {
            const int kk = idx >> 4;
            const int f4 = idx & 15;
            const int j = (cb + kk) * 10;
            const size_t row = (size_t)(j * BATCH + b) * ldk + hcol;
            ((float4*)sK)[kk * 16 + f4] = ((const float4*)(Kb + row))[f4];
            ((float4*)sV)[kk * 16 + f4] = ((const float4*)(Vb + row))[f4];
        }
        __syncthreads();
        for (int kk = 0; kk < cnt; kk++) {
            const float4* kp = (const float4*)(sK + kk * 64 + dimbase);
            float p = 0.f;
#pragma unroll
            for (int f = 0; f < 4; f++) {
                float4 kv = kp[f];
                p += q[f].x * kv.x + q[f].y * kv.y + q[f].z * kv.z + q[f].w * kv.w;
            }
            p += __shfl_xor_sync(0xffffffffu, p, 1);
            p += __shfl_xor_sync(0xffffffffu, p, 2);
            const float e = __expf(p * 0.125f);
            lsum += e;
            const float4* vp = (const float4*)(sV + kk * 64 + dimbase);
#pragma unroll
            for (int f = 0; f < 4; f++) {
                float4 vv = vp[f];
                acc[f].x += e * vv.x; acc[f].y += e * vv.y;
                acc[f].z += e * vv.z; acc[f].w += e * vv.w;
            }
        }
    }

    // ---- band keys (|j - i| <= 5, excluding j % 10 == 0) via gmem ----
#pragma unroll
    for (int dj = -WWIN; dj <= WWIN; dj++) {
        const int j = qi + dj;
        const bool valid = (j >= 0) && (j < S_LEN) && (j % 10 != 0);
        const int jc = min(max(j, 0), S_LEN - 1);
        const size_t row = (size_t)(jc * BATCH + b) * ldk + hcol + dimbase;
        const float4* kp = (const float4*)(Kb + row);
        float p = 0.f;
#pragma unroll
        for (int f = 0; f < 4; f++) {
            float4 kv = kp[f];
            p += q[f].x * kv.x + q[f].y * kv.y + q[f].z * kv.z + q[f].w * kv.w;
        }
        p += __shfl_xor_sync(0xffffffffu, p, 1);
        p += __shfl_xor_sync(0xffffffffu, p, 2);
        const float e = valid ? __expf(p * 0.125f) : 0.f;
        lsum += e;
        const float4* vp = (const float4*)(Vb + row);
#pragma unroll
        for (int f = 0; f < 4; f++) {
            float4 vv = vp[f];
            acc[f].x += e * vv.x; acc[f].y += e * vv.y;
            acc[f].z += e * vv.z; acc[f].w += e * vv.w;
        }
    }

    const float inv = 1.f / lsum;
    float4* op = (float4*)(O + (size_t)(qi * BATCH + b) * DMODEL + hcol + dimbase);
#pragma unroll
    for (int f = 0; f < 4; f++) {
        float4 o;
        o.x = tf32_rna(acc[f].x * inv);
        o.y = tf32_rna(acc[f].y * inv);
        o.z = tf32_rna(acc[f].z * inv);
        o.w = tf32_rna(acc[f].w * inv);
        op[f] = o;
    }
}

// ---------------- layernorm, block per row (dual output: full + tf32) ----------------
__global__ __launch_bounds__(128) void ln_kernel(
    const float* __restrict__ in, const float* __restrict__ g,
    const float* __restrict__ b, float* __restrict__ out,
    float* __restrict__ out_r)
{
    const int row = blockIdx.x;
    const int t = threadIdx.x;
    const float4 v = ((const float4*)(in + (size_t)row * DMODEL))[t];

    float s  = v.x + v.y + v.z + v.w;
    float ss = v.x * v.x + v.y * v.y + v.z * v.z + v.w * v.w;
#pragma unroll
    for (int off = 16; off; off >>= 1) {
        s  += __shfl_xor_sync(0xffffffffu, s, off);
        ss += __shfl_xor_sync(0xffffffffu, ss, off);
    }
    __shared__ float red[8];
    const int wid = t >> 5;
    if ((t & 31) == 0) { red[wid] = s; red[4 + wid] = ss; }
    __syncthreads();
    s  = red[0] + red[1] + red[2] + red[3];
    ss = red[4] + red[5] + red[6] + red[7];

    const float mean = s * (1.f / DMODEL);
    const float var  = ss * (1.f / DMODEL) - mean * mean;
    const float rs = rsqrtf(var + LN_EPS);

    const float4 gg = ((const float4*)g)[t];
    const float4 bb = ((const float4*)b)[t];
    float4 o;
    o.x = (v.x - mean) * rs * gg.x + bb.x;
    o.y = (v.y - mean) * rs * gg.y + bb.y;
    o.z = (v.z - mean) * rs * gg.z + bb.z;
    o.w = (v.w - mean) * rs * gg.w + bb.w;
    ((float4*)(out + (size_t)row * DMODEL))[t] = o;
    if (out_r) {
        float4 orr;
        orr.x = tf32_rna(o.x); orr.y = tf32_rna(o.y);
        orr.z = tf32_rna(o.z); orr.w = tf32_rna(o.w);
        ((float4*)(out_r + (size_t)row * DMODEL))[t] = orr;
    }
}

// ---------------- launch ----------------
extern "C" void kernel_launch(void* const* d_in, const int* in_sizes, int n_in,
                              void* d_out, int out_size)
{
    const float* x   = (const float*)d_in[0];
    const float* enc = (const float*)d_in[1];
    const float* sa_Wq = (const float*)d_in[2];
    const float* sa_Wk = (const float*)d_in[3];
    const float* sa_Wv = (const float*)d_in[4];
    const float* sa_Wo = (const float*)d_in[5];
    const float* sa_bq = (const float*)d_in[6];
    const float* sa_bk = (const float*)d_in[7];
    const float* sa_bv = (const float*)d_in[8];
    const float* sa_bo = (const float*)d_in[9];
    const float* ca_Wq = (const float*)d_in[10];
    const float* ca_Wk = (const float*)d_in[11];
    const float* ca_Wv = (const float*)d_in[12];
    const float* ca_Wo = (const float*)d_in[13];
    const float* ca_bq = (const float*)d_in[14];
    const float* ca_bk = (const float*)d_in[15];
    const float* ca_bv = (const float*)d_in[16];
    const float* ca_bo = (const float*)d_in[17];
    const float* ff_W1 = (const float*)d_in[18];
    const float* ff_W2 = (const float*)d_in[19];
    const float* ff_b1 = (const float*)d_in[20];
    const float* ff_b2 = (const float*)d_in[21];
    const float* ln1_g = (const float*)d_in[22];
    const float* ln1_b = (const float*)d_in[23];
    const float* ln2_g = (const float*)d_in[24];
    const float* ln2_b = (const float*)d_in[25];
    const float* ln3_g = (const float*)d_in[26];
    const float* ln3_b = (const float*)d_in[27];
    float* out = (float*)d_out;

    float *qkv, *attn, *tmp, *x1, *x2, *ff, *kv, *qc, *wr, *xr, *encr, *x1r, *x2r, *bsa, *bca;
    cudaGetSymbolAddress((void**)&qkv, g_qkv);
    cudaGetSymbolAddress((void**)&attn, g_attn);
    cudaGetSymbolAddress((void**)&tmp, g_tmp);
    cudaGetSymbolAddress((void**)&x1, g_x1);
    cudaGetSymbolAddress((void**)&x2, g_x2);
    cudaGetSymbolAddress((void**)&ff, g_ff);
    cudaGetSymbolAddress((void**)&kv, g_kv);
    cudaGetSymbolAddress((void**)&qc, g_qc);
    cudaGetSymbolAddress((void**)&wr, g_wr);
    cudaGetSymbolAddress((void**)&xr, g_xr);
    cudaGetSymbolAddress((void**)&encr, g_encr);
    cudaGetSymbolAddress((void**)&x1r, g_x1r);
    cudaGetSymbolAddress((void**)&x2r, g_x2r);
    cudaGetSymbolAddress((void**)&bsa, g_bsa);
    cudaGetSymbolAddress((void**)&bca, g_bca);

    const int PW = DMODEL * DMODEL;
    float* r_saWqkv = wr + 0 * PW;            // Wq|Wk|Wv contiguous
    float* r_saWo   = wr + 3 * PW;
    float* r_caWq   = wr + 4 * PW;
    float* r_caWkv  = wr + 5 * PW;            // Wk|Wv contiguous
    float* r_caWo   = wr + 7 * PW;
    float* r_ffW1   = wr + 8 * PW;
    float* r_ffW2   = wr + 8 * PW + FFDIM * DMODEL;

    CvtArgs ca;
    const float* srcs[NCVT] = { sa_Wq, sa_Wk, sa_Wv, sa_Wo, ca_Wq, ca_Wk, ca_Wv, ca_Wo,
                                ff_W1, ff_W2, x, enc,
                                sa_bq, sa_bk, sa_bv, ca_bk, ca_bv };
    float* dsts[NCVT] = { r_saWqkv, r_saWqkv + PW, r_saWqkv + 2 * PW, r_saWo,
                          r_caWq, r_caWkv, r_caWkv + PW, r_caWo,
                          r_ffW1, r_ffW2, xr, encr,
                          bsa, bsa + DMODEL, bsa + 2 * DMODEL, bca, bca + DMODEL };
    int ns[NCVT] = { PW, PW, PW, PW, PW, PW, PW, PW,
                     FFDIM * DMODEL, FFDIM * DMODEL, NTOK * DMODEL, NTOK * DMODEL,
                     DMODEL, DMODEL, DMODEL, DMODEL, DMODEL };
    int rnds[NCVT] = { 1,1,1,1, 1,1,1,1, 1,1, 1,1, 0,0,0, 0,0 };
    for (int i = 0; i < NCVT; i++) {
        ca.src[i] = srcs[i]; ca.dst[i] = dsts[i]; ca.n4[i] = ns[i] / 4; ca.rnd[i] = rnds[i];
    }

    cudaFuncSetAttribute(gemm_tf32_kernel,
                         cudaFuncAttributeMaxDynamicSharedMemorySize, GEMM_SMEM_BYTES);

    const dim3 gblk(128);
    const dim3 gQKV(3 * DMODEL / GBN, NTOK / GBM);   // (24, 64) = 1536 blocks
    const dim3 gKV(2 * DMODEL / GBN, NTOK / GBM);    // (16, 64) = 1024
    const dim3 gProj(DMODEL / GBN, NTOK / GBM);      // (8, 64)  = 512
    const dim3 gFF1(FFDIM / GBN, NTOK / GBM);        // (32, 64) = 2048
    const dim3 gAttn(S_LEN / AQ_PER_BLOCK, BATCH * NHEAD);  // (32, 16)

    cvt_kernel<<<dim3(128, NCVT), 256>>>(ca);

    // ---- self attention ----
    gemm_tf32_kernel<<<gQKV, gblk, GEMM_SMEM_BYTES>>>(xr, r_saWqkv, bsa, nullptr, qkv, NTOK, 3 * DMODEL, DMODEL, 0);
    attn4_kernel<<<gAttn, 256>>>(qkv, 3 * DMODEL, qkv + DMODEL, qkv + 2 * DMODEL, 3 * DMODEL, attn);
    gemm_tf32_kernel<<<gProj, gblk, GEMM_SMEM_BYTES>>>(attn, r_saWo, sa_bo, x, tmp, NTOK, DMODEL, DMODEL, EF_RES);
    ln_kernel<<<NTOK, 128>>>(tmp, ln1_g, ln1_b, x1, x1r);

    // ---- cross attention ----
    gemm_tf32_kernel<<<gKV, gblk, GEMM_SMEM_BYTES>>>(encr, r_caWkv, bca, nullptr, kv, NTOK, 2 * DMODEL, DMODEL, 0);
    gemm_tf32_kernel<<<gProj, gblk, GEMM_SMEM_BYTES>>>(x1r, r_caWq, ca_bq, nullptr, qc, NTOK, DMODEL, DMODEL, 0);
    attn4_kernel<<<gAttn, 256>>>(qc, DMODEL, kv, kv + DMODEL, 2 * DMODEL, attn);
    gemm_tf32_kernel<<<gProj, gblk, GEMM_SMEM_BYTES>>>(attn, r_caWo, ca_bo, x1, tmp, NTOK, DMODEL, DMODEL, EF_RES);
    ln_kernel<<<NTOK, 128>>>(tmp, ln2_g, ln2_b, x2, x2r);

    // ---- feed forward ----
    gemm_tf32_kernel<<<gFF1, gblk, GEMM_SMEM_BYTES>>>(x2r, r_ffW1, ff_b1, nullptr, ff, NTOK, FFDIM, DMODEL, EF_RELU | EF_ROUND);
    gemm_tf32_kernel<<<gProj, gblk, GEMM_SMEM_BYTES>>>(ff, r_ffW2, ff_b2, x2, tmp, NTOK, DMODEL, FFDIM, EF_RES);
    ln_kernel<<<NTOK, 128>>>(tmp, ln3_g, ln3_b, out, nullptr);
}

// round 7
// speedup vs baseline: 1.0768x; 1.0768x over previous
#include <cuda_runtime.h>
#include <cuda_bf16.h>
#include <math.h>
#include <stdint.h>

// Problem constants
#define S_LEN 2048
#define BATCH 2
#define DMODEL 512
#define NHEAD 8
#define HDIM 64
#define FFDIM 2048
#define NTOK (S_LEN * BATCH)   // 4096
#define WWIN 5
#define LN_EPS 1e-5f

// ---------------- scratch (no allocations allowed) ----------------
__device__ float g_qkv[(size_t)NTOK * 3 * DMODEL];   // [tok, q|k|v]
__device__ float g_attn[(size_t)NTOK * DMODEL];      // rounded tf32
__device__ float g_ff[(size_t)NTOK * FFDIM];         // rounded tf32
__device__ float g_kv[(size_t)NTOK * 2 * DMODEL];    // cross K|V
__device__ float g_qc[(size_t)NTOK * DMODEL];        // cross Q
__device__ float g_part[4 * (size_t)NTOK * DMODEL];  // split-K partials (32 MB)
__device__ float g_x1[(size_t)NTOK * DMODEL];
__device__ float g_x2[(size_t)NTOK * DMODEL];
// rounded tf32 copies for MMA inputs
__device__ float g_wr[4194304];
__device__ float g_xr[(size_t)NTOK * DMODEL];
__device__ float g_encr[(size_t)NTOK * DMODEL];
__device__ float g_x1r[(size_t)NTOK * DMODEL];
__device__ float g_x2r[(size_t)NTOK * DMODEL];
// concatenated biases
__device__ float g_bsa[3 * DMODEL];
__device__ float g_bca[2 * DMODEL];

// epilogue flags
#define EF_RELU    1
#define EF_ROUND   8

__device__ __forceinline__ float tf32_rna(float x) {
    uint32_t u;
    asm("cvt.rna.tf32.f32 %0, %1;" : "=r"(u) : "f"(x));
    return __uint_as_float(u);
}

// ---------------- copy/round kernel ----------------
#define NCVT 17
struct CvtArgs {
    const float* src[NCVT];
    float* dst[NCVT];
    int n4[NCVT];
    int rnd[NCVT];
};

__global__ __launch_bounds__(256) void cvt_kernel(CvtArgs args) {
    const int ti = blockIdx.y;
    const int n4 = args.n4[ti];
    const int rnd = args.rnd[ti];
    const float4* src = (const float4*)args.src[ti];
    float4* dst = (float4*)args.dst[ti];
    for (int i = blockIdx.x * 256 + threadIdx.x; i < n4; i += gridDim.x * 256) {
        float4 v = src[i];
        if (rnd) {
            v.x = tf32_rna(v.x); v.y = tf32_rna(v.y);
            v.z = tf32_rna(v.z); v.w = tf32_rna(v.w);
        }
        dst[i] = v;
    }
}

// ---------------- tf32 tensor-core GEMM (round-3 proven shape) ----------------
// C[m,n] = sum_k A[m,k]*Bw[n,k] (+bias[n]).  BM=128, BN=64, BK=32, 256 threads.
// 8 warps (4M x 2N), warp tile 32x32. Split-K via gridDim.z: z-th slice of K,
// output at C + z*M*N (bias must be null for split-K launches).
#define GBM 128
#define GBN 64
#define GBK 32
#define APAD 36
#define A_BUF (GBM * APAD)   // 4608 floats
#define B_BUF (GBN * APAD)   // 2304 floats
#define GEMM_SMEM_BYTES ((2 * A_BUF + 2 * B_BUF) * 4)   // 55296

__device__ __forceinline__ void cp16(void* dst, const void* src) {
    uint32_t d = (uint32_t)__cvta_generic_to_shared(dst);
    asm volatile("cp.async.cg.shared.global [%0], [%1], 16;" :: "r"(d), "l"(src));
}

__device__ __forceinline__ void mma_tf32(float* d, const uint32_t* a, const uint32_t* b) {
    asm volatile(
        "mma.sync.aligned.m16n8k8.row.col.f32.tf32.tf32.f32 "
        "{%0,%1,%2,%3},{%4,%5,%6,%7},{%8,%9},{%0,%1,%2,%3};"
        : "+f"(d[0]), "+f"(d[1]), "+f"(d[2]), "+f"(d[3])
        : "r"(a[0]), "r"(a[1]), "r"(a[2]), "r"(a[3]), "r"(b[0]), "r"(b[1]));
}

__global__ __launch_bounds__(256) void gemm_tf32_kernel(
    const float* __restrict__ A, const float* __restrict__ Bw,
    const float* __restrict__ bias,
    float* __restrict__ C, int M, int N, int K, int flags)
{
    extern __shared__ float smem[];
    float* As[2] = { smem, smem + A_BUF };
    float* Bs[2] = { smem + 2 * A_BUF, smem + 2 * A_BUF + B_BUF };

    const int t = threadIdx.x;
    const int lane = t & 31;
    const int warp = t >> 5;
    const int wm = warp >> 1;        // 0..3
    const int wn = warp & 1;         // 0..1
    const int r = lane >> 2;         // 0..7
    const int c = lane & 3;          // 0..3

    const int bm = blockIdx.y * GBM;
    const int bn = blockIdx.x * GBN;
    // split-K: this block covers K-slice [koff, koff + K)
    const int koff = blockIdx.z * K;
    float* Cz = C + (size_t)blockIdx.z * M * N;

    // load mapping
    const int arow = t >> 1;                 // 0..127, 2 threads/row
    const int aq = (t & 1) * 4;              // float4 base (4 per thread)
    const int brow = t >> 2;                 // 0..63, 4 threads/row
    const int bq = (t & 3) * 2;              // float4 base (2 per thread)

    const float* Abase = A + (size_t)(bm + arow) * (K * gridDim.z) + koff + aq * 4;
    const float* Bbase = Bw + (size_t)(bn + brow) * (K * gridDim.z) + koff + bq * 4;
    float* AsRow[2] = { As[0] + arow * APAD + aq * 4, As[1] + arow * APAD + aq * 4 };
    float* BsRow[2] = { Bs[0] + brow * APAD + bq * 4, Bs[1] + brow * APAD + bq * 4 };

    float acc[2][4][4];
#pragma unroll
    for (int i = 0; i < 2; i++)
#pragma unroll
        for (int j = 0; j < 4; j++)
#pragma unroll
            for (int l = 0; l < 4; l++) acc[i][j][l] = 0.f;

    const int TK = K >> 5;

    {
#pragma unroll
        for (int j = 0; j < 4; j++)
            cp16(AsRow[0] + j * 4, Abase + j * 4);
#pragma unroll
        for (int j = 0; j < 2; j++)
            cp16(BsRow[0] + j * 4, Bbase + j * 4);
        asm volatile("cp.async.commit_group;");
    }

    const int amb = wm * 32;
    const int bnb = wn * 32;

    for (int kt = 0; kt < TK; kt++) {
        const int cur = kt & 1;
        const int nxt = cur ^ 1;
        if (kt + 1 < TK) {
            const int ko = (kt + 1) * GBK;
#pragma unroll
            for (int j = 0; j < 4; j++)
                cp16(AsRow[nxt] + j * 4, Abase + ko + j * 4);
#pragma unroll
            for (int j = 0; j < 2; j++)
                cp16(BsRow[nxt] + j * 4, Bbase + ko + j * 4);
            asm volatile("cp.async.commit_group;");
            asm volatile("cp.async.wait_group 1;");
        } else {
            asm volatile("cp.async.wait_group 0;");
        }
        __syncthreads();

        const float* Ac = As[cur];
        const float* Bc = Bs[cur];

        uint32_t af[2][2][4];   // [buf][mt][4]
        uint32_t bf[2][4][2];   // [buf][nt][2]

        // prefetch ks=0 fragments
#pragma unroll
        for (int mt = 0; mt < 2; mt++) {
            const int mb = amb + mt * 16;
            af[0][mt][0] = __float_as_uint(Ac[(mb + r) * APAD + c]);
            af[0][mt][1] = __float_as_uint(Ac[(mb + r + 8) * APAD + c]);
            af[0][mt][2] = __float_as_uint(Ac[(mb + r) * APAD + c + 4]);
            af[0][mt][3] = __float_as_uint(Ac[(mb + r + 8) * APAD + c + 4]);
        }
#pragma unroll
        for (int nt = 0; nt < 4; nt++) {
            const int nb = bnb + nt * 8;
            bf[0][nt][0] = __float_as_uint(Bc[(nb + r) * APAD + c]);
            bf[0][nt][1] = __float_as_uint(Bc[(nb + r) * APAD + c + 4]);
        }

#pragma unroll
        for (int ks = 0; ks < 4; ks++) {
            const int cb = ks & 1;
            if (ks < 3) {
                const int k0 = (ks + 1) * 8;
                const int nb2 = cb ^ 1;
#pragma unroll
                for (int mt = 0; mt < 2; mt++) {
                    const int mb = amb + mt * 16;
                    af[nb2][mt][0] = __float_as_uint(Ac[(mb + r) * APAD + k0 + c]);
                    af[nb2][mt][1] = __float_as_uint(Ac[(mb + r + 8) * APAD + k0 + c]);
                    af[nb2][mt][2] = __float_as_uint(Ac[(mb + r) * APAD + k0 + c + 4]);
                    af[nb2][mt][3] = __float_as_uint(Ac[(mb + r + 8) * APAD + k0 + c + 4]);
                }
#pragma unroll
                for (int nt = 0; nt < 4; nt++) {
                    const int nb = bnb + nt * 8;
                    bf[nb2][nt][0] = __float_as_uint(Bc[(nb + r) * APAD + k0 + c]);
                    bf[nb2][nt][1] = __float_as_uint(Bc[(nb + r) * APAD + k0 + c + 4]);
                }
            }
#pragma unroll
            for (int mt = 0; mt < 2; mt++)
#pragma unroll
                for (int nt = 0; nt < 4; nt++)
                    mma_tf32(acc[mt][nt], af[cb][mt], bf[cb][nt]);
        }
        __syncthreads();
    }

    // epilogue: plain row-major store
#pragma unroll
    for (int mt = 0; mt < 2; mt++) {
        const int m0 = bm + amb + mt * 16 + r;
#pragma unroll
        for (int nt = 0; nt < 4; nt++) {
            const int n0 = bn + bnb + nt * 8 + c * 2;
#pragma unroll
            for (int e = 0; e < 4; e++) {
                const int m = m0 + (e >> 1) * 8;
                const int n = n0 + (e & 1);
                float v = acc[mt][nt][e];
                if (bias) v += bias[n];
                if (flags & EF_RELU) v = fmaxf(v, 0.f);
                if (flags & EF_ROUND) v = tf32_rna(v);
                Cz[(size_t)m * N + n] = v;
            }
        }
    }
}

// ---------------- sparse attention, 4 threads per query ----------------
// Token-row layout: row(tok s, batch b) = s*2+b. Head h at cols [h*64, h*64+64).
// allowed(j|i) = |j-i| <= 5  OR  j % 10 == 0. fixed-max softmax (scores bounded).
#define AQ_PER_BLOCK 64
#define STRIDED_KEYS 205
#define KTILE 32

__global__ __launch_bounds__(256) void attn4_kernel(
    const float* __restrict__ Qb, int ldq,
    const float* __restrict__ Kb, const float* __restrict__ Vb, int ldk,
    float* __restrict__ O)
{
    __shared__ float sK[KTILE * 64];
    __shared__ float sV[KTILE * 64];

    const int t = threadIdx.x;
    const int bh = blockIdx.y;
    const int b = bh >> 3;
    const int h = bh & 7;
    const int hcol = h * HDIM;
    const int qi = blockIdx.x * AQ_PER_BLOCK + (t >> 2);
    const int dimbase = (t & 3) * 16;

    float4 q[4];
    const float4* qp = (const float4*)(Qb + (size_t)(qi * BATCH + b) * ldq + hcol + dimbase);
#pragma unroll
    for (int f = 0; f < 4; f++) q[f] = qp[f];

    float4 acc[4];
#pragma unroll
    for (int f = 0; f < 4; f++) acc[f] = make_float4(0.f, 0.f, 0.f, 0.f);
    float lsum = 0.f;

    for (int cb = 0; cb < STRIDED_KEYS; cb += KTILE) {
        const int cnt = min(KTILE, STRIDED_KEYS - cb);
        __syncthreads();
        for (int idx = t; idx < cnt * 16; idx += 256) {
            const int kk = idx >> 4;
            const int f4 = idx & 15;
            const int j = (cb + kk) * 10;
            const size_t row = (size_t)(j * BATCH + b) * ldk + hcol;
            ((float4*)sK)[kk * 16 + f4] = ((const float4*)(Kb + row))[f4];
            ((float4*)sV)[kk * 16 + f4] = ((const float4*)(Vb + row))[f4];
        }
        __syncthreads();
        for (int kk = 0; kk < cnt; kk++) {
            const float4* kp = (const float4*)(sK + kk * 64 + dimbase);
            float p = 0.f;
#pragma unroll
            for (int f = 0; f < 4; f++) {
                float4 kv = kp[f];
                p += q[f].x * kv.x + q[f].y * kv.y + q[f].z * kv.z + q[f].w * kv.w;
            }
            p += __shfl_xor_sync(0xffffffffu, p, 1);
            p += __shfl_xor_sync(0xffffffffu, p, 2);
            const float e = __expf(p * 0.125f);
            lsum += e;
            const float4* vp = (const float4*)(sV + kk * 64 + dimbase);
#pragma unroll
            for (int f = 0; f < 4; f++) {
                float4 vv = vp[f];
                acc[f].x += e * vv.x; acc[f].y += e * vv.y;
                acc[f].z += e * vv.z; acc[f].w += e * vv.w;
            }
        }
    }

#pragma unroll
    for (int dj = -WWIN; dj <= WWIN; dj++) {
        const int j = qi + dj;
        const bool valid = (j >= 0) && (j < S_LEN) && (j % 10 != 0);
        const int jc = min(max(j, 0), S_LEN - 1);
        const size_t row = (size_t)(jc * BATCH + b) * ldk + hcol + dimbase;
        const float4* kp = (const float4*)(Kb + row);
        float p = 0.f;
#pragma unroll
        for (int f = 0; f < 4; f++) {
            float4 kv = kp[f];
            p += q[f].x * kv.x + q[f].y * kv.y + q[f].z * kv.z + q[f].w * kv.w;
        }
        p += __shfl_xor_sync(0xffffffffu, p, 1);
        p += __shfl_xor_sync(0xffffffffu, p, 2);
        const float e = valid ? __expf(p * 0.125f) : 0.f;
        lsum += e;
        const float4* vp = (const float4*)(Vb + row);
#pragma unroll
        for (int f = 0; f < 4; f++) {
            float4 vv = vp[f];
            acc[f].x += e * vv.x; acc[f].y += e * vv.y;
            acc[f].z += e * vv.z; acc[f].w += e * vv.w;
        }
    }

    const float inv = 1.f / lsum;
    float4* op = (float4*)(O + (size_t)(qi * BATCH + b) * DMODEL + hcol + dimbase);
#pragma unroll
    for (int f = 0; f < 4; f++) {
        float4 o;
        o.x = tf32_rna(acc[f].x * inv);
        o.y = tf32_rna(acc[f].y * inv);
        o.z = tf32_rna(acc[f].z * inv);
        o.w = tf32_rna(acc[f].w * inv);
        op[f] = o;
    }
}

// ---------------- ln_sum: sum split-K partials + bias + residual, then LN ----------------
__global__ __launch_bounds__(128) void ln_sum_kernel(
    const float* __restrict__ parts, int nsplit,
    const float* __restrict__ bias, const float* __restrict__ res,
    const float* __restrict__ g, const float* __restrict__ b,
    float* __restrict__ out, float* __restrict__ out_r)
{
    const int row = blockIdx.x;
    const int t = threadIdx.x;
    const size_t pstride = (size_t)NTOK * DMODEL;
    const size_t off = (size_t)row * DMODEL;

    float4 v = ((const float4*)(parts + off))[t];
#pragma unroll 3
    for (int s = 1; s < nsplit; s++) {
        float4 p = ((const float4*)(parts + s * pstride + off))[t];
        v.x += p.x; v.y += p.y; v.z += p.z; v.w += p.w;
    }
    const float4 bi = ((const float4*)bias)[t];
    const float4 rr = ((const float4*)(res + off))[t];
    v.x += bi.x + rr.x; v.y += bi.y + rr.y;
    v.z += bi.z + rr.z; v.w += bi.w + rr.w;

    float s  = v.x + v.y + v.z + v.w;
    float ss = v.x * v.x + v.y * v.y + v.z * v.z + v.w * v.w;
#pragma unroll
    for (int off2 = 16; off2; off2 >>= 1) {
        s  += __shfl_xor_sync(0xffffffffu, s, off2);
        ss += __shfl_xor_sync(0xffffffffu, ss, off2);
    }
    __shared__ float red[8];
    const int wid = t >> 5;
    if ((t & 31) == 0) { red[wid] = s; red[4 + wid] = ss; }
    __syncthreads();
    s  = red[0] + red[1] + red[2] + red[3];
    ss = red[4] + red[5] + red[6] + red[7];

    const float mean = s * (1.f / DMODEL);
    const float var  = ss * (1.f / DMODEL) - mean * mean;
    const float rs = rsqrtf(var + LN_EPS);

    const float4 gg = ((const float4*)g)[t];
    const float4 bb = ((const float4*)b)[t];
    float4 o;
    o.x = (v.x - mean) * rs * gg.x + bb.x;
    o.y = (v.y - mean) * rs * gg.y + bb.y;
    o.z = (v.z - mean) * rs * gg.z + bb.z;
    o.w = (v.w - mean) * rs * gg.w + bb.w;
    ((float4*)(out + off))[t] = o;
    if (out_r) {
        float4 orr;
        orr.x = tf32_rna(o.x); orr.y = tf32_rna(o.y);
        orr.z = tf32_rna(o.z); orr.w = tf32_rna(o.w);
        ((float4*)(out_r + off))[t] = orr;
    }
}

// ---------------- launch ----------------
extern "C" void kernel_launch(void* const* d_in, const int* in_sizes, int n_in,
                              void* d_out, int out_size)
{
    const float* x   = (const float*)d_in[0];
    const float* enc = (const float*)d_in[1];
    const float* sa_Wq = (const float*)d_in[2];
    const float* sa_Wk = (const float*)d_in[3];
    const float* sa_Wv = (const float*)d_in[4];
    const float* sa_Wo = (const float*)d_in[5];
    const float* sa_bq = (const float*)d_in[6];
    const float* sa_bk = (const float*)d_in[7];
    const float* sa_bv = (const float*)d_in[8];
    const float* sa_bo = (const float*)d_in[9];
    const float* ca_Wq = (const float*)d_in[10];
    const float* ca_Wk = (const float*)d_in[11];
    const float* ca_Wv = (const float*)d_in[12];
    const float* ca_Wo = (const float*)d_in[13];
    const float* ca_bq = (const float*)d_in[14];
    const float* ca_bk = (const float*)d_in[15];
    const float* ca_bv = (const float*)d_in[16];
    const float* ca_bo = (const float*)d_in[17];
    const float* ff_W1 = (const float*)d_in[18];
    const float* ff_W2 = (const float*)d_in[19];
    const float* ff_b1 = (const float*)d_in[20];
    const float* ff_b2 = (const float*)d_in[21];
    const float* ln1_g = (const float*)d_in[22];
    const float* ln1_b = (const float*)d_in[23];
    const float* ln2_g = (const float*)d_in[24];
    const float* ln2_b = (const float*)d_in[25];
    const float* ln3_g = (const float*)d_in[26];
    const float* ln3_b = (const float*)d_in[27];
    float* out = (float*)d_out;

    float *qkv, *attn, *ff, *kv, *qc, *part, *x1, *x2, *wr, *xr, *encr, *x1r, *x2r, *bsa, *bca;
    cudaGetSymbolAddress((void**)&qkv, g_qkv);
    cudaGetSymbolAddress((void**)&attn, g_attn);
    cudaGetSymbolAddress((void**)&ff, g_ff);
    cudaGetSymbolAddress((void**)&kv, g_kv);
    cudaGetSymbolAddress((void**)&qc, g_qc);
    cudaGetSymbolAddress((void**)&part, g_part);
    cudaGetSymbolAddress((void**)&x1, g_x1);
    cudaGetSymbolAddress((void**)&x2, g_x2);
    cudaGetSymbolAddress((void**)&wr, g_wr);
    cudaGetSymbolAddress((void**)&xr, g_xr);
    cudaGetSymbolAddress((void**)&encr, g_encr);
    cudaGetSymbolAddress((void**)&x1r, g_x1r);
    cudaGetSymbolAddress((void**)&x2r, g_x2r);
    cudaGetSymbolAddress((void**)&bsa, g_bsa);
    cudaGetSymbolAddress((void**)&bca, g_bca);

    const int PW = DMODEL * DMODEL;
    float* r_saWqkv = wr + 0 * PW;            // Wq|Wk|Wv contiguous
    float* r_saWo   = wr + 3 * PW;
    float* r_caWq   = wr + 4 * PW;
    float* r_caWkv  = wr + 5 * PW;            // Wk|Wv contiguous
    float* r_caWo   = wr + 7 * PW;
    float* r_ffW1   = wr + 8 * PW;
    float* r_ffW2   = wr + 8 * PW + FFDIM * DMODEL;

    CvtArgs ca;
    const float* srcs[NCVT] = { sa_Wq, sa_Wk, sa_Wv, sa_Wo, ca_Wq, ca_Wk, ca_Wv, ca_Wo,
                                ff_W1, ff_W2, x, enc,
                                sa_bq, sa_bk, sa_bv, ca_bk, ca_bv };
    float* dsts[NCVT] = { r_saWqkv, r_saWqkv + PW, r_saWqkv + 2 * PW, r_saWo,
                          r_caWq, r_caWkv, r_caWkv + PW, r_caWo,
                          r_ffW1, r_ffW2, xr, encr,
                          bsa, bsa + DMODEL, bsa + 2 * DMODEL, bca, bca + DMODEL };
    int ns[NCVT] = { PW, PW, PW, PW, PW, PW, PW, PW,
                     FFDIM * DMODEL, FFDIM * DMODEL, NTOK * DMODEL, NTOK * DMODEL,
                     DMODEL, DMODEL, DMODEL, DMODEL, DMODEL };
    int rnds[NCVT] = { 1,1,1,1, 1,1,1,1, 1,1, 1,1, 0,0,0, 0,0 };
    for (int i = 0; i < NCVT; i++) {
        ca.src[i] = srcs[i]; ca.dst[i] = dsts[i]; ca.n4[i] = ns[i] / 4; ca.rnd[i] = rnds[i];
    }

    cudaFuncSetAttribute(gemm_tf32_kernel,
                         cudaFuncAttributeMaxDynamicSharedMemorySize, GEMM_SMEM_BYTES);

    const dim3 gblk(256);
    const dim3 gQKV(3 * DMODEL / GBN, NTOK / GBM, 1);    // (24, 32) = 768 blocks
    const dim3 gKV(2 * DMODEL / GBN, NTOK / GBM, 1);     // (16, 32) = 512
    const dim3 gProj(DMODEL / GBN, NTOK / GBM, 1);       // (8, 32)  = 256
    const dim3 gProjS2(DMODEL / GBN, NTOK / GBM, 2);     // 512 (split-K 2, K=256 each)
    const dim3 gFF1(FFDIM / GBN, NTOK / GBM, 1);         // (32, 32) = 1024
    const dim3 gFF2S4(DMODEL / GBN, NTOK / GBM, 4);      // 1024 (split-K 4, K=512 each)
    const dim3 gAttn(S_LEN / AQ_PER_BLOCK, BATCH * NHEAD);

    cvt_kernel<<<dim3(128, NCVT), 256>>>(ca);

    // ---- self attention ----
    gemm_tf32_kernel<<<gQKV, gblk, GEMM_SMEM_BYTES>>>(xr, r_saWqkv, bsa, qkv, NTOK, 3 * DMODEL, DMODEL, 0);
    attn4_kernel<<<gAttn, 256>>>(qkv, 3 * DMODEL, qkv + DMODEL, qkv + 2 * DMODEL, 3 * DMODEL, attn);
    gemm_tf32_kernel<<<gProjS2, gblk, GEMM_SMEM_BYTES>>>(attn, r_saWo, nullptr, part, NTOK, DMODEL, DMODEL / 2, 0);
    ln_sum_kernel<<<NTOK, 128>>>(part, 2, sa_bo, x, ln1_g, ln1_b, x1, x1r);

    // ---- cross attention ----
    gemm_tf32_kernel<<<gKV, gblk, GEMM_SMEM_BYTES>>>(encr, r_caWkv, bca, kv, NTOK, 2 * DMODEL, DMODEL, 0);
    gemm_tf32_kernel<<<gProj, gblk, GEMM_SMEM_BYTES>>>(x1r, r_caWq, ca_bq, qc, NTOK, DMODEL, DMODEL, 0);
    attn4_kernel<<<gAttn, 256>>>(qc, DMODEL, kv, kv + DMODEL, 2 * DMODEL, attn);
    gemm_tf32_kernel<<<gProjS2, gblk, GEMM_SMEM_BYTES>>>(attn, r_caWo, nullptr, part, NTOK, DMODEL, DMODEL / 2, 0);
    ln_sum_kernel<<<NTOK, 128>>>(part, 2, ca_bo, x1, ln2_g, ln2_b, x2, x2r);

    // ---- feed forward ----
    gemm_tf32_kernel<<<gFF1, gblk, GEMM_SMEM_BYTES>>>(x2r, r_ffW1, ff_b1, ff, NTOK, FFDIM, DMODEL, EF_RELU | EF_ROUND);
    gemm_tf32_kernel<<<gFF2S4, gblk, GEMM_SMEM_BYTES>>>(ff, r_ffW2, nullptr, part, NTOK, DMODEL, FFDIM / 4, 0);
    ln_sum_kernel<<<NTOK, 128>>>(part, 4, ff_b2, x2, ln3_g, ln3_b, out, nullptr);
}

// round 8
// speedup vs baseline: 1.1500x; 1.0679x over previous
#include <cuda_runtime.h>
#include <cuda_bf16.h>
#include <math.h>
#include <stdint.h>

// Problem constants
#define S_LEN 2048
#define BATCH 2
#define DMODEL 512
#define NHEAD 8
#define HDIM 64
#define FFDIM 2048
#define NTOK (S_LEN * BATCH)   // 4096
#define WWIN 5
#define LN_EPS 1e-5f

// ---------------- scratch (no allocations allowed) ----------------
__device__ float g_qkv[(size_t)NTOK * 3 * DMODEL];   // [tok, q|k|v]
__device__ float g_attn[(size_t)NTOK * DMODEL];      // rounded tf32
__device__ float g_ff[(size_t)NTOK * FFDIM];         // rounded tf32
__device__ float g_kv[(size_t)NTOK * 2 * DMODEL];    // cross K|V
__device__ float g_qc[(size_t)NTOK * DMODEL];        // cross Q
__device__ float g_part[(size_t)NTOK * DMODEL];      // pre-LN GEMM output
__device__ float g_x1[(size_t)NTOK * DMODEL];
__device__ float g_x2[(size_t)NTOK * DMODEL];
// rounded tf32 copies for MMA inputs
__device__ float g_wr[4194304];
__device__ float g_xr[(size_t)NTOK * DMODEL];
__device__ float g_encr[(size_t)NTOK * DMODEL];
__device__ float g_x1r[(size_t)NTOK * DMODEL];
__device__ float g_x2r[(size_t)NTOK * DMODEL];
// concatenated biases
__device__ float g_bsa[3 * DMODEL];
__device__ float g_bca[2 * DMODEL];

// epilogue flags
#define EF_RELU    1
#define EF_ROUND   8

__device__ __forceinline__ float tf32_rna(float x) {
    uint32_t u;
    asm("cvt.rna.tf32.f32 %0, %1;" : "=r"(u) : "f"(x));
    return __uint_as_float(u);
}

// ---------------- copy/round kernel ----------------
#define NCVT 17
struct CvtArgs {
    const float* src[NCVT];
    float* dst[NCVT];
    int n4[NCVT];
    int rnd[NCVT];
};

__global__ __launch_bounds__(256) void cvt_kernel(CvtArgs args) {
    const int ti = blockIdx.y;
    const int n4 = args.n4[ti];
    const int rnd = args.rnd[ti];
    const float4* src = (const float4*)args.src[ti];
    float4* dst = (float4*)args.dst[ti];
    for (int i = blockIdx.x * 256 + threadIdx.x; i < n4; i += gridDim.x * 256) {
        float4 v = src[i];
        if (rnd) {
            v.x = tf32_rna(v.x); v.y = tf32_rna(v.y);
            v.z = tf32_rna(v.z); v.w = tf32_rna(v.w);
        }
        dst[i] = v;
    }
}

// ---------------- tf32 tensor-core GEMM, 4-stage cp.async pipeline ----------------
// C[m,n] = sum_k A[m,k]*Bw[n,k] (+bias[n]).  BM=128, BN=64, BK=32, 256 threads.
// 8 warps (4M x 2N), warp tile 32x32, register fragment double buffering.
// Requires K >= 3*GBK (true for all launches here: K in {512, 2048}).
#define GBM 128
#define GBN 64
#define GBK 32
#define APAD 36
#define A_BUF (GBM * APAD)            // 4608 floats
#define B_BUF (GBN * APAD)            // 2304 floats
#define NSTAGE 4
#define STAGE_FLOATS (A_BUF + B_BUF)  // 6912
#define GEMM_SMEM_BYTES (NSTAGE * STAGE_FLOATS * 4)   // 110592

__device__ __forceinline__ void cp16(void* dst, const void* src) {
    uint32_t d = (uint32_t)__cvta_generic_to_shared(dst);
    asm volatile("cp.async.cg.shared.global [%0], [%1], 16;" :: "r"(d), "l"(src));
}

__device__ __forceinline__ void mma_tf32(float* d, const uint32_t* a, const uint32_t* b) {
    asm volatile(
        "mma.sync.aligned.m16n8k8.row.col.f32.tf32.tf32.f32 "
        "{%0,%1,%2,%3},{%4,%5,%6,%7},{%8,%9},{%0,%1,%2,%3};"
        : "+f"(d[0]), "+f"(d[1]), "+f"(d[2]), "+f"(d[3])
        : "r"(a[0]), "r"(a[1]), "r"(a[2]), "r"(a[3]), "r"(b[0]), "r"(b[1]));
}

__global__ __launch_bounds__(256) void gemm_tf32_kernel(
    const float* __restrict__ A, const float* __restrict__ Bw,
    const float* __restrict__ bias,
    float* __restrict__ C, int M, int N, int K, int flags)
{
    extern __shared__ float smem[];

    const int t = threadIdx.x;
    const int lane = t & 31;
    const int warp = t >> 5;
    const int wm = warp >> 1;        // 0..3
    const int wn = warp & 1;         // 0..1
    const int r = lane >> 2;         // 0..7
    const int c = lane & 3;          // 0..3

    const int bm = blockIdx.y * GBM;
    const int bn = blockIdx.x * GBN;

    // load mapping
    const int arow = t >> 1;                 // 0..127, 2 threads/row
    const int aq = (t & 1) * 4;              // float4 base (4 per thread)
    const int brow = t >> 2;                 // 0..63, 4 threads/row
    const int bq = (t & 3) * 2;              // float4 base (2 per thread)

    const float* Abase = A + (size_t)(bm + arow) * K + aq * 4;
    const float* Bbase = Bw + (size_t)(bn + brow) * K + bq * 4;
    const int aoff = arow * APAD + aq * 4;
    const int boff = A_BUF + brow * APAD + bq * 4;

    float acc[2][4][4];
#pragma unroll
    for (int i = 0; i < 2; i++)
#pragma unroll
        for (int j = 0; j < 4; j++)
#pragma unroll
            for (int l = 0; l < 4; l++) acc[i][j][l] = 0.f;

    const int TK = K >> 5;

    // prologue: fill stages 0..2
#pragma unroll
    for (int s = 0; s < NSTAGE - 1; s++) {
        float* st = smem + s * STAGE_FLOATS;
        const int ko = s * GBK;
#pragma unroll
        for (int j = 0; j < 4; j++)
            cp16(st + aoff + j * 4, Abase + ko + j * 4);
#pragma unroll
        for (int j = 0; j < 2; j++)
            cp16(st + boff + j * 4, Bbase + ko + j * 4);
        asm volatile("cp.async.commit_group;");
    }

    const int amb = wm * 32;
    const int bnb = wn * 32;

    for (int kt = 0; kt < TK; kt++) {
        // stage kt ready: total commits = kt+3, wait<=2 -> first kt+1 groups done
        asm volatile("cp.async.wait_group 2;");
        __syncthreads();

        // issue loads for stage kt+3 into ring slot (kt+3)%4 (read last at kt-1)
        if (kt + NSTAGE - 1 < TK) {
            float* st = smem + ((kt + NSTAGE - 1) & (NSTAGE - 1)) * STAGE_FLOATS;
            const int ko = (kt + NSTAGE - 1) * GBK;
#pragma unroll
            for (int j = 0; j < 4; j++)
                cp16(st + aoff + j * 4, Abase + ko + j * 4);
#pragma unroll
            for (int j = 0; j < 2; j++)
                cp16(st + boff + j * 4, Bbase + ko + j * 4);
        }
        asm volatile("cp.async.commit_group;");   // always commit (may be empty)

        const float* Ac = smem + (kt & (NSTAGE - 1)) * STAGE_FLOATS;
        const float* Bc = Ac + A_BUF;

        uint32_t af[2][2][4];   // [buf][mt][4]
        uint32_t bf[2][4][2];   // [buf][nt][2]

        // prefetch ks=0 fragments
#pragma unroll
        for (int mt = 0; mt < 2; mt++) {
            const int mb = amb + mt * 16;
            af[0][mt][0] = __float_as_uint(Ac[(mb + r) * APAD + c]);
            af[0][mt][1] = __float_as_uint(Ac[(mb + r + 8) * APAD + c]);
            af[0][mt][2] = __float_as_uint(Ac[(mb + r) * APAD + c + 4]);
            af[0][mt][3] = __float_as_uint(Ac[(mb + r + 8) * APAD + c + 4]);
        }
#pragma unroll
        for (int nt = 0; nt < 4; nt++) {
            const int nb = bnb + nt * 8;
            bf[0][nt][0] = __float_as_uint(Bc[(nb + r) * APAD + c]);
            bf[0][nt][1] = __float_as_uint(Bc[(nb + r) * APAD + c + 4]);
        }

#pragma unroll
        for (int ks = 0; ks < 4; ks++) {
            const int cb = ks & 1;
            if (ks < 3) {
                const int k0 = (ks + 1) * 8;
                const int nb2 = cb ^ 1;
#pragma unroll
                for (int mt = 0; mt < 2; mt++) {
                    const int mb = amb + mt * 16;
                    af[nb2][mt][0] = __float_as_uint(Ac[(mb + r) * APAD + k0 + c]);
                    af[nb2][mt][1] = __float_as_uint(Ac[(mb + r + 8) * APAD + k0 + c]);
                    af[nb2][mt][2] = __float_as_uint(Ac[(mb + r) * APAD + k0 + c + 4]);
                    af[nb2][mt][3] = __float_as_uint(Ac[(mb + r + 8) * APAD + k0 + c + 4]);
                }
#pragma unroll
                for (int nt = 0; nt < 4; nt++) {
                    const int nb = bnb + nt * 8;
                    bf[nb2][nt][0] = __float_as_uint(Bc[(nb + r) * APAD + k0 + c]);
                    bf[nb2][nt][1] = __float_as_uint(Bc[(nb + r) * APAD + k0 + c + 4]);
                }
            }
#pragma unroll
            for (int mt = 0; mt < 2; mt++)
#pragma unroll
                for (int nt = 0; nt < 4; nt++)
                    mma_tf32(acc[mt][nt], af[cb][mt], bf[cb][nt]);
        }
    }

    // epilogue: plain row-major store
#pragma unroll
    for (int mt = 0; mt < 2; mt++) {
        const int m0 = bm + amb + mt * 16 + r;
#pragma unroll
        for (int nt = 0; nt < 4; nt++) {
            const int n0 = bn + bnb + nt * 8 + c * 2;
#pragma unroll
            for (int e = 0; e < 4; e++) {
                const int m = m0 + (e >> 1) * 8;
                const int n = n0 + (e & 1);
                float v = acc[mt][nt][e];
                if (bias) v += bias[n];
                if (flags & EF_RELU) v = fmaxf(v, 0.f);
                if (flags & EF_ROUND) v = tf32_rna(v);
                C[(size_t)m * N + n] = v;
            }
        }
    }
}

// ---------------- sparse attention, 4 threads per query ----------------
// Token-row layout: row(tok s, batch b) = s*2+b. Head h at cols [h*64, h*64+64).
// allowed(j|i) = |j-i| <= 5  OR  j % 10 == 0. fixed-max softmax (scores bounded).
#define AQ_PER_BLOCK 64
#define STRIDED_KEYS 205
#define KTILE 32

__global__ __launch_bounds__(256) void attn4_kernel(
    const float* __restrict__ Qb, int ldq,
    const float* __restrict__ Kb, const float* __restrict__ Vb, int ldk,
    float* __restrict__ O)
{
    __shared__ float sK[KTILE * 64];
    __shared__ float sV[KTILE * 64];

    const int t = threadIdx.x;
    const int bh = blockIdx.y;
    const int b = bh >> 3;
    const int h = bh & 7;
    const int hcol = h * HDIM;
    const int qi = blockIdx.x * AQ_PER_BLOCK + (t >> 2);
    const int dimbase = (t & 3) * 16;

    float4 q[4];
    const float4* qp = (const float4*)(Qb + (size_t)(qi * BATCH + b) * ldq + hcol + dimbase);
#pragma unroll
    for (int f = 0; f < 4; f++) q[f] = qp[f];

    float4 acc[4];
#pragma unroll
    for (int f = 0; f < 4; f++) acc[f] = make_float4(0.f, 0.f, 0.f, 0.f);
    float lsum = 0.f;

    for (int cb = 0; cb < STRIDED_KEYS; cb += KTILE) {
        const int cnt = min(KTILE, STRIDED_KEYS - cb);
        __syncthreads();
        for (int idx = t; idx < cnt * 16; idx += 256) {
            const int kk = idx >> 4;
            const int f4 = idx & 15;
            const int j = (cb + kk) * 10;
            const size_t row = (size_t)(j * BATCH + b) * ldk + hcol;
            ((float4*)sK)[kk * 16 + f4] = ((const float4*)(Kb + row))[f4];
            ((float4*)sV)[kk * 16 + f4] = ((const float4*)(Vb + row))[f4];
        }
        __syncthreads();
        for (int kk = 0; kk < cnt; kk++) {
            const float4* kp = (const float4*)(sK + kk * 64 + dimbase);
            float p = 0.f;
#pragma unroll
            for (int f = 0; f < 4; f++) {
                float4 kv = kp[f];
                p += q[f].x * kv.x + q[f].y * kv.y + q[f].z * kv.z + q[f].w * kv.w;
            }
            p += __shfl_xor_sync(0xffffffffu, p, 1);
            p += __shfl_xor_sync(0xffffffffu, p, 2);
            const float e = __expf(p * 0.125f);
            lsum += e;
            const float4* vp = (const float4*)(sV + kk * 64 + dimbase);
#pragma unroll
            for (int f = 0; f < 4; f++) {
                float4 vv = vp[f];
                acc[f].x += e * vv.x; acc[f].y += e * vv.y;
                acc[f].z += e * vv.z; acc[f].w += e * vv.w;
            }
        }
    }

#pragma unroll
    for (int dj = -WWIN; dj <= WWIN; dj++) {
        const int j = qi + dj;
        const bool valid = (j >= 0) && (j < S_LEN) && (j % 10 != 0);
        const int jc = min(max(j, 0), S_LEN - 1);
        const size_t row = (size_t)(jc * BATCH + b) * ldk + hcol + dimbase;
        const float4* kp = (const float4*)(Kb + row);
        float p = 0.f;
#pragma unroll
        for (int f = 0; f < 4; f++) {
            float4 kv = kp[f];
            p += q[f].x * kv.x + q[f].y * kv.y + q[f].z * kv.z + q[f].w * kv.w;
        }
        p += __shfl_xor_sync(0xffffffffu, p, 1);
        p += __shfl_xor_sync(0xffffffffu, p, 2);
        const float e = valid ? __expf(p * 0.125f) : 0.f;
        lsum += e;
        const float4* vp = (const float4*)(Vb + row);
#pragma unroll
        for (int f = 0; f < 4; f++) {
            float4 vv = vp[f];
            acc[f].x += e * vv.x; acc[f].y += e * vv.y;
            acc[f].z += e * vv.z; acc[f].w += e * vv.w;
        }
    }

    const float inv = 1.f / lsum;
    float4* op = (float4*)(O + (size_t)(qi * BATCH + b) * DMODEL + hcol + dimbase);
#pragma unroll
    for (int f = 0; f < 4; f++) {
        float4 o;
        o.x = tf32_rna(acc[f].x * inv);
        o.y = tf32_rna(acc[f].y * inv);
        o.z = tf32_rna(acc[f].z * inv);
        o.w = tf32_rna(acc[f].w * inv);
        op[f] = o;
    }
}

// ---------------- ln_sum: GEMM output + bias + residual, then LN ----------------
__global__ __launch_bounds__(128) void ln_sum_kernel(
    const float* __restrict__ gin,
    const float* __restrict__ bias, const float* __restrict__ res,
    const float* __restrict__ g, const float* __restrict__ b,
    float* __restrict__ out, float* __restrict__ out_r)
{
    const int row = blockIdx.x;
    const int t = threadIdx.x;
    const size_t off = (size_t)row * DMODEL;

    float4 v = ((const float4*)(gin + off))[t];
    const float4 bi = ((const float4*)bias)[t];
    const float4 rr = ((const float4*)(res + off))[t];
    v.x += bi.x + rr.x; v.y += bi.y + rr.y;
    v.z += bi.z + rr.z; v.w += bi.w + rr.w;

    float s  = v.x + v.y + v.z + v.w;
    float ss = v.x * v.x + v.y * v.y + v.z * v.z + v.w * v.w;
#pragma unroll
    for (int off2 = 16; off2; off2 >>= 1) {
        s  += __shfl_xor_sync(0xffffffffu, s, off2);
        ss += __shfl_xor_sync(0xffffffffu, ss, off2);
    }
    __shared__ float red[8];
    const int wid = t >> 5;
    if ((t & 31) == 0) { red[wid] = s; red[4 + wid] = ss; }
    __syncthreads();
    s  = red[0] + red[1] + red[2] + red[3];
    ss = red[4] + red[5] + red[6] + red[7];

    const float mean = s * (1.f / DMODEL);
    const float var  = ss * (1.f / DMODEL) - mean * mean;
    const float rs = rsqrtf(var + LN_EPS);

    const float4 gg = ((const float4*)g)[t];
    const float4 bb = ((const float4*)b)[t];
    float4 o;
    o.x = (v.x - mean) * rs * gg.x + bb.x;
    o.y = (v.y - mean) * rs * gg.y + bb.y;
    o.z = (v.z - mean) * rs * gg.z + bb.z;
    o.w = (v.w - mean) * rs * gg.w + bb.w;
    ((float4*)(out + off))[t] = o;
    if (out_r) {
        float4 orr;
        orr.x = tf32_rna(o.x); orr.y = tf32_rna(o.y);
        orr.z = tf32_rna(o.z); orr.w = tf32_rna(o.w);
        ((float4*)(out_r + off))[t] = orr;
    }
}

// ---------------- launch ----------------
extern "C" void kernel_launch(void* const* d_in, const int* in_sizes, int n_in,
                              void* d_out, int out_size)
{
    const float* x   = (const float*)d_in[0];
    const float* enc = (const float*)d_in[1];
    const float* sa_Wq = (const float*)d_in[2];
    const float* sa_Wk = (const float*)d_in[3];
    const float* sa_Wv = (const float*)d_in[4];
    const float* sa_Wo = (const float*)d_in[5];
    const float* sa_bq = (const float*)d_in[6];
    const float* sa_bk = (const float*)d_in[7];
    const float* sa_bv = (const float*)d_in[8];
    const float* sa_bo = (const float*)d_in[9];
    const float* ca_Wq = (const float*)d_in[10];
    const float* ca_Wk = (const float*)d_in[11];
    const float* ca_Wv = (const float*)d_in[12];
    const float* ca_Wo = (const float*)d_in[13];
    const float* ca_bq = (const float*)d_in[14];
    const float* ca_bk = (const float*)d_in[15];
    const float* ca_bv = (const float*)d_in[16];
    const float* ca_bo = (const float*)d_in[17];
    const float* ff_W1 = (const float*)d_in[18];
    const float* ff_W2 = (const float*)d_in[19];
    const float* ff_b1 = (const float*)d_in[20];
    const float* ff_b2 = (const float*)d_in[21];
    const float* ln1_g = (const float*)d_in[22];
    const float* ln1_b = (const float*)d_in[23];
    const float* ln2_g = (const float*)d_in[24];
    const float* ln2_b = (const float*)d_in[25];
    const float* ln3_g = (const float*)d_in[26];
    const float* ln3_b = (const float*)d_in[27];
    float* out = (float*)d_out;

    float *qkv, *attn, *ff, *kv, *qc, *part, *x1, *x2, *wr, *xr, *encr, *x1r, *x2r, *bsa, *bca;
    cudaGetSymbolAddress((void**)&qkv, g_qkv);
    cudaGetSymbolAddress((void**)&attn, g_attn);
    cudaGetSymbolAddress((void**)&ff, g_ff);
    cudaGetSymbolAddress((void**)&kv, g_kv);
    cudaGetSymbolAddress((void**)&qc, g_qc);
    cudaGetSymbolAddress((void**)&part, g_part);
    cudaGetSymbolAddress((void**)&x1, g_x1);
    cudaGetSymbolAddress((void**)&x2, g_x2);
    cudaGetSymbolAddress((void**)&wr, g_wr);
    cudaGetSymbolAddress((void**)&xr, g_xr);
    cudaGetSymbolAddress((void**)&encr, g_encr);
    cudaGetSymbolAddress((void**)&x1r, g_x1r);
    cudaGetSymbolAddress((void**)&x2r, g_x2r);
    cudaGetSymbolAddress((void**)&bsa, g_bsa);
    cudaGetSymbolAddress((void**)&bca, g_bca);

    const int PW = DMODEL * DMODEL;
    float* r_saWqkv = wr + 0 * PW;            // Wq|Wk|Wv contiguous
    float* r_saWo   = wr + 3 * PW;
    float* r_caWq   = wr + 4 * PW;
    float* r_caWkv  = wr + 5 * PW;            // Wk|Wv contiguous
    float* r_caWo   = wr + 7 * PW;
    float* r_ffW1   = wr + 8 * PW;
    float* r_ffW2   = wr + 8 * PW + FFDIM * DMODEL;

    CvtArgs ca;
    const float* srcs[NCVT] = { sa_Wq, sa_Wk, sa_Wv, sa_Wo, ca_Wq, ca_Wk, ca_Wv, ca_Wo,
                                ff_W1, ff_W2, x, enc,
                                sa_bq, sa_bk, sa_bv, ca_bk, ca_bv };
    float* dsts[NCVT] = { r_saWqkv, r_saWqkv + PW, r_saWqkv + 2 * PW, r_saWo,
                          r_caWq, r_caWkv, r_caWkv + PW, r_caWo,
                          r_ffW1, r_ffW2, xr, encr,
                          bsa, bsa + DMODEL, bsa + 2 * DMODEL, bca, bca + DMODEL };
    int ns[NCVT] = { PW, PW, PW, PW, PW, PW, PW, PW,
                     FFDIM * DMODEL, FFDIM * DMODEL, NTOK * DMODEL, NTOK * DMODEL,
                     DMODEL, DMODEL, DMODEL, DMODEL, DMODEL };
    int rnds[NCVT] = { 1,1,1,1, 1,1,1,1, 1,1, 1,1, 0,0,0, 0,0 };
    for (int i = 0; i < NCVT; i++) {
        ca.src[i] = srcs[i]; ca.dst[i] = dsts[i]; ca.n4[i] = ns[i] / 4; ca.rnd[i] = rnds[i];
    }

    cudaFuncSetAttribute(gemm_tf32_kernel,
                         cudaFuncAttributeMaxDynamicSharedMemorySize, GEMM_SMEM_BYTES);

    const dim3 gblk(256);
    const dim3 gQKV(3 * DMODEL / GBN, NTOK / GBM);   // (24, 32) = 768 blocks
    const dim3 gKV(2 * DMODEL / GBN, NTOK / GBM);    // (16, 32) = 512
    const dim3 gProj(DMODEL / GBN, NTOK / GBM);      // (8, 32)  = 256
    const dim3 gFF1(FFDIM / GBN, NTOK / GBM);        // (32, 32) = 1024
    const dim3 gAttn(S_LEN / AQ_PER_BLOCK, BATCH * NHEAD);

    cvt_kernel<<<dim3(128, NCVT), 256>>>(ca);

    // ---- self attention ----
    gemm_tf32_kernel<<<gQKV, gblk, GEMM_SMEM_BYTES>>>(xr, r_saWqkv, bsa, qkv, NTOK, 3 * DMODEL, DMODEL, 0);
    attn4_kernel<<<gAttn, 256>>>(qkv, 3 * DMODEL, qkv + DMODEL, qkv + 2 * DMODEL, 3 * DMODEL, attn);
    gemm_tf32_kernel<<<gProj, gblk, GEMM_SMEM_BYTES>>>(attn, r_saWo, nullptr, part, NTOK, DMODEL, DMODEL, 0);
    ln_sum_kernel<<<NTOK, 128>>>(part, sa_bo, x, ln1_g, ln1_b, x1, x1r);

    // ---- cross attention ----
    gemm_tf32_kernel<<<gKV, gblk, GEMM_SMEM_BYTES>>>(encr, r_caWkv, bca, kv, NTOK, 2 * DMODEL, DMODEL, 0);
    gemm_tf32_kernel<<<gProj, gblk, GEMM_SMEM_BYTES>>>(x1r, r_caWq, ca_bq, qc, NTOK, DMODEL, DMODEL, 0);
    attn4_kernel<<<gAttn, 256>>>(qc, DMODEL, kv, kv + DMODEL, 2 * DMODEL, attn);
    gemm_tf32_kernel<<<gProj, gblk, GEMM_SMEM_BYTES>>>(attn, r_caWo, nullptr, part, NTOK, DMODEL, DMODEL, 0);
    ln_sum_kernel<<<NTOK, 128>>>(part, ca_bo, x1, ln2_g, ln2_b, x2, x2r);

    // ---- feed forward ----
    gemm_tf32_kernel<<<gFF1, gblk, GEMM_SMEM_BYTES>>>(x2r, r_ffW1, ff_b1, ff, NTOK, FFDIM, DMODEL, EF_RELU | EF_ROUND);
    gemm_tf32_kernel<<<gProj, gblk, GEMM_SMEM_BYTES>>>(ff, r_ffW2, nullptr, part, NTOK, DMODEL, FFDIM, 0);
    ln_sum_kernel<<<NTOK, 128>>>(part, ff_b2, x2, ln3_g, ln3_b, out, nullptr);
}

// round 9
// speedup vs baseline: 1.5012x; 1.3054x over previous
#include <cuda_runtime.h>
#include <cuda_bf16.h>
#include <math.h>
#include <stdint.h>

// Problem constants
#define S_LEN 2048
#define BATCH 2
#define DMODEL 512
#define NHEAD 8
#define HDIM 64
#define FFDIM 2048
#define NTOK (S_LEN * BATCH)   // 4096
#define WWIN 5
#define LN_EPS 1e-5f

// ---------------- scratch (no allocations allowed) ----------------
__device__ float g_qkv[(size_t)NTOK * 3 * DMODEL];       // self Q|K|V fp32
__device__ float g_kv[(size_t)NTOK * 2 * DMODEL];        // cross K|V fp32
__device__ float g_qc[(size_t)NTOK * DMODEL];            // cross Q fp32
__device__ float g_part[(size_t)NTOK * DMODEL];          // pre-LN GEMM out fp32
__device__ float g_x1[(size_t)NTOK * DMODEL];
__device__ float g_x2[(size_t)NTOK * DMODEL];
// bf16 GEMM inputs
__device__ __nv_bfloat16 g_wb[4194304];                  // all weights bf16
__device__ __nv_bfloat16 g_xb[(size_t)NTOK * DMODEL];
__device__ __nv_bfloat16 g_encb[(size_t)NTOK * DMODEL];
__device__ __nv_bfloat16 g_x1b[(size_t)NTOK * DMODEL];
__device__ __nv_bfloat16 g_x2b[(size_t)NTOK * DMODEL];
__device__ __nv_bfloat16 g_attnb[(size_t)NTOK * DMODEL];
__device__ __nv_bfloat16 g_ffb[(size_t)NTOK * FFDIM];
// concatenated biases (fp32)
__device__ float g_bsa[3 * DMODEL];
__device__ float g_bca[2 * DMODEL];

// epilogue flags
#define EF_RELU    1
#define EF_BF16OUT 2

// ---------------- convert/copy kernel ----------------
#define NCVT 17
struct CvtArgs {
    const float* src[NCVT];
    void* dst[NCVT];
    int n4[NCVT];     // element count / 4
    int tobf[NCVT];   // 1 -> fp32->bf16, 0 -> fp32 copy
};

__global__ __launch_bounds__(256) void cvt_kernel(CvtArgs args) {
    const int ti = blockIdx.y;
    const int n4 = args.n4[ti];
    const int tobf = args.tobf[ti];
    const float4* src = (const float4*)args.src[ti];
    for (int i = blockIdx.x * 256 + threadIdx.x; i < n4; i += gridDim.x * 256) {
        float4 v = src[i];
        if (tobf) {
            __nv_bfloat162* d = (__nv_bfloat162*)args.dst[ti];
            d[2 * i]     = __nv_bfloat162(__float2bfloat16_rn(v.x), __float2bfloat16_rn(v.y));
            d[2 * i + 1] = __nv_bfloat162(__float2bfloat16_rn(v.z), __float2bfloat16_rn(v.w));
        } else {
            ((float4*)args.dst[ti])[i] = v;
        }
    }
}

// ---------------- bf16 tensor-core GEMM, 4-stage cp.async + ldmatrix ----------------
// C[m,n] = sum_k A[m,k]*Bw[n,k] (+bias[n]).  BM=128, BN=64, BK=32, 256 threads.
// 8 warps (4M x 2N), warp tile 32x32 via mma.m16n8k16.bf16, fragments via ldmatrix.x4.
#define GBM 128
#define GBN 64
#define GBK 32
#define APADB 40                        // bf16 per smem row (80B: LDSM conflict-free)
#define A_ELE (GBM * APADB)             // 5120 bf16
#define B_ELE (GBN * APADB)             // 2560 bf16
#define A_BYTES (A_ELE * 2)             // 10240
#define STAGE_BYTES ((A_ELE + B_ELE) * 2)   // 15360
#define NSTAGE 4
#define GEMM_SMEM_BYTES (NSTAGE * STAGE_BYTES)   // 61440

__device__ __forceinline__ void cp16(void* dst, const void* src) {
    uint32_t d = (uint32_t)__cvta_generic_to_shared(dst);
    asm volatile("cp.async.cg.shared.global [%0], [%1], 16;" :: "r"(d), "l"(src));
}

__device__ __forceinline__ void ldsm_x4(uint32_t* r, uint32_t addr) {
    asm volatile("ldmatrix.sync.aligned.m8n8.x4.shared.b16 {%0,%1,%2,%3}, [%4];"
        : "=r"(r[0]), "=r"(r[1]), "=r"(r[2]), "=r"(r[3]) : "r"(addr));
}

__device__ __forceinline__ void mma_bf16(float* d, const uint32_t* a, const uint32_t* b) {
    asm volatile(
        "mma.sync.aligned.m16n8k16.row.col.f32.bf16.bf16.f32 "
        "{%0,%1,%2,%3},{%4,%5,%6,%7},{%8,%9},{%0,%1,%2,%3};"
        : "+f"(d[0]), "+f"(d[1]), "+f"(d[2]), "+f"(d[3])
        : "r"(a[0]), "r"(a[1]), "r"(a[2]), "r"(a[3]), "r"(b[0]), "r"(b[1]));
}

__global__ __launch_bounds__(256) void gemm_bf16_kernel(
    const __nv_bfloat16* __restrict__ A, const __nv_bfloat16* __restrict__ Bw,
    const float* __restrict__ bias,
    float* __restrict__ C, int M, int N, int K, int flags)
{
    extern __shared__ __nv_bfloat16 smem[];
    const uint32_t sbase = (uint32_t)__cvta_generic_to_shared(smem);

    const int t = threadIdx.x;
    const int lane = t & 31;
    const int warp = t >> 5;
    const int wm = warp >> 1;        // 0..3
    const int wn = warp & 1;         // 0..1
    const int r = lane >> 2;         // 0..7
    const int c = lane & 3;          // 0..3

    const int bm = blockIdx.y * GBM;
    const int bn = blockIdx.x * GBN;

    // cp.async load mapping (bf16 units): A 128x32: thread -> row t>>1, half t&1 (2x16B)
    const int arow = t >> 1;
    const int ahalf = (t & 1) * 16;
    // B 64x32: thread -> row t>>2, quarter t&3 (1x16B)
    const int brow = t >> 2;
    const int bq = (t & 3) * 8;

    const __nv_bfloat16* Abase = A + (size_t)(bm + arow) * K + ahalf;
    const __nv_bfloat16* Bbase = Bw + (size_t)(bn + brow) * K + bq;
    const int aoff = arow * APADB + ahalf;          // bf16 units within stage
    const int boff = A_ELE + brow * APADB + bq;

    // ldmatrix per-thread address components (bytes within stage)
    const uint32_t a_off = (uint32_t)(((wm * 32 + (lane & 15)) * APADB + ((lane & 16) >> 1)) * 2);
    const uint32_t b_off = (uint32_t)(A_BYTES +
        ((wn * 32 + (lane & 7) + ((lane & 16) >> 1)) * APADB + (lane & 8)) * 2);

    float acc[2][4][4];
#pragma unroll
    for (int i = 0; i < 2; i++)
#pragma unroll
        for (int j = 0; j < 4; j++)
#pragma unroll
            for (int l = 0; l < 4; l++) acc[i][j][l] = 0.f;

    const int TK = K >> 5;

    // prologue: fill stages 0..2
#pragma unroll
    for (int s = 0; s < NSTAGE - 1; s++) {
        __nv_bfloat16* st = smem + s * (A_ELE + B_ELE);
        const int ko = s * GBK;
        cp16(st + aoff, Abase + ko);
        cp16(st + aoff + 8, Abase + ko + 8);
        cp16(st + boff, Bbase + ko);
        asm volatile("cp.async.commit_group;");
    }

    for (int kt = 0; kt < TK; kt++) {
        asm volatile("cp.async.wait_group 2;");
        __syncthreads();

        if (kt + NSTAGE - 1 < TK) {
            __nv_bfloat16* st = smem + ((kt + NSTAGE - 1) & (NSTAGE - 1)) * (A_ELE + B_ELE);
            const int ko = (kt + NSTAGE - 1) * GBK;
            cp16(st + aoff, Abase + ko);
            cp16(st + aoff + 8, Abase + ko + 8);
            cp16(st + boff, Bbase + ko);
        }
        asm volatile("cp.async.commit_group;");

        const uint32_t sa = sbase + (uint32_t)((kt & (NSTAGE - 1)) * STAGE_BYTES);
        const uint32_t aaddr = sa + a_off;
        const uint32_t baddr = sa + b_off;

#pragma unroll
        for (int ks = 0; ks < 2; ks++) {
            const uint32_t kb = ks * 32;   // 16 bf16 = 32 bytes
            uint32_t a0[4], a1[4], b01[4], b23[4];
            ldsm_x4(a0, aaddr + kb);            // mt=0 (rows wm*32+0..15)
            ldsm_x4(a1, aaddr + kb + 1280);     // mt=1 (+16 rows * 80B)
            ldsm_x4(b01, baddr + kb);           // nt0,nt1 (n +0..15)
            ldsm_x4(b23, baddr + kb + 1280);    // nt2,nt3 (n +16..31)
            mma_bf16(acc[0][0], a0, b01);
            mma_bf16(acc[0][1], a0, b01 + 2);
            mma_bf16(acc[0][2], a0, b23);
            mma_bf16(acc[0][3], a0, b23 + 2);
            mma_bf16(acc[1][0], a1, b01);
            mma_bf16(acc[1][1], a1, b01 + 2);
            mma_bf16(acc[1][2], a1, b23);
            mma_bf16(acc[1][3], a1, b23 + 2);
        }
    }

    // epilogue
#pragma unroll
    for (int mt = 0; mt < 2; mt++) {
        const int m0 = bm + wm * 32 + mt * 16 + r;
#pragma unroll
        for (int nt = 0; nt < 4; nt++) {
            const int n0 = bn + wn * 32 + nt * 8 + c * 2;
#pragma unroll
            for (int e = 0; e < 4; e++) {
                const int m = m0 + (e >> 1) * 8;
                const int n = n0 + (e & 1);
                float v = acc[mt][nt][e];
                if (bias) v += bias[n];
                if (flags & EF_RELU) v = fmaxf(v, 0.f);
                if (flags & EF_BF16OUT)
                    ((__nv_bfloat16*)C)[(size_t)m * N + n] = __float2bfloat16_rn(v);
                else
                    C[(size_t)m * N + n] = v;
            }
        }
    }
}

// ---------------- sparse attention, 4 threads per query, bf16 output ----------------
// Token-row layout: row(tok s, batch b) = s*2+b. Head h at cols [h*64, h*64+64).
// allowed(j|i) = |j-i| <= 5  OR  j % 10 == 0. fixed-max softmax (scores bounded).
#define AQ_PER_BLOCK 64
#define STRIDED_KEYS 205
#define KTILE 32

__global__ __launch_bounds__(256) void attn4_kernel(
    const float* __restrict__ Qb, int ldq,
    const float* __restrict__ Kb, const float* __restrict__ Vb, int ldk,
    __nv_bfloat16* __restrict__ O)
{
    __shared__ float sK[KTILE * 64];
    __shared__ float sV[KTILE * 64];

    const int t = threadIdx.x;
    const int bh = blockIdx.y;
    const int b = bh >> 3;
    const int h = bh & 7;
    const int hcol = h * HDIM;
    const int qi = blockIdx.x * AQ_PER_BLOCK + (t >> 2);
    const int dimbase = (t & 3) * 16;

    float4 q[4];
    const float4* qp = (const float4*)(Qb + (size_t)(qi * BATCH + b) * ldq + hcol + dimbase);
#pragma unroll
    for (int f = 0; f < 4; f++) q[f] = qp[f];

    float4 acc[4];
#pragma unroll
    for (int f = 0; f < 4; f++) acc[f] = make_float4(0.f, 0.f, 0.f, 0.f);
    float lsum = 0.f;

    for (int cb = 0; cb < STRIDED_KEYS; cb += KTILE) {
        const int cnt = min(KTILE, STRIDED_KEYS - cb);
        __syncthreads();
        for (int idx = t; idx < cnt * 16; idx += 256) {
            const int kk = idx >> 4;
            const int f4 = idx & 15;
            const int j = (cb + kk) * 10;
            const size_t row = (size_t)(j * BATCH + b) * ldk + hcol;
            ((float4*)sK)[kk * 16 + f4] = ((const float4*)(Kb + row))[f4];
            ((float4*)sV)[kk * 16 + f4] = ((const float4*)(Vb + row))[f4];
        }
        __syncthreads();
        for (int kk = 0; kk < cnt; kk++) {
            const float4* kp = (const float4*)(sK + kk * 64 + dimbase);
            float p = 0.f;
#pragma unroll
            for (int f = 0; f < 4; f++) {
                float4 kv = kp[f];
                p += q[f].x * kv.x + q[f].y * kv.y + q[f].z * kv.z + q[f].w * kv.w;
            }
            p += __shfl_xor_sync(0xffffffffu, p, 1);
            p += __shfl_xor_sync(0xffffffffu, p, 2);
            const float e = __expf(p * 0.125f);
            lsum += e;
            const float4* vp = (const float4*)(sV + kk * 64 + dimbase);
#pragma unroll
            for (int f = 0; f < 4; f++) {
                float4 vv = vp[f];
                acc[f].x += e * vv.x; acc[f].y += e * vv.y;
                acc[f].z += e * vv.z; acc[f].w += e * vv.w;
            }
        }
    }

#pragma unroll
    for (int dj = -WWIN; dj <= WWIN; dj++) {
        const int j = qi + dj;
        const bool valid = (j >= 0) && (j < S_LEN) && (j % 10 != 0);
        const int jc = min(max(j, 0), S_LEN - 1);
        const size_t row = (size_t)(jc * BATCH + b) * ldk + hcol + dimbase;
        const float4* kp = (const float4*)(Kb + row);
        float p = 0.f;
#pragma unroll
        for (int f = 0; f < 4; f++) {
            float4 kv = kp[f];
            p += q[f].x * kv.x + q[f].y * kv.y + q[f].z * kv.z + q[f].w * kv.w;
        }
        p += __shfl_xor_sync(0xffffffffu, p, 1);
        p += __shfl_xor_sync(0xffffffffu, p, 2);
        const float e = valid ? __expf(p * 0.125f) : 0.f;
        lsum += e;
        const float4* vp = (const float4*)(Vb + row);
#pragma unroll
        for (int f = 0; f < 4; f++) {
            float4 vv = vp[f];
            acc[f].x += e * vv.x; acc[f].y += e * vv.y;
            acc[f].z += e * vv.z; acc[f].w += e * vv.w;
        }
    }

    const float inv = 1.f / lsum;
    __nv_bfloat162* op = (__nv_bfloat162*)(O + (size_t)(qi * BATCH + b) * DMODEL + hcol + dimbase);
#pragma unroll
    for (int f = 0; f < 4; f++) {
        op[2 * f]     = __nv_bfloat162(__float2bfloat16_rn(acc[f].x * inv),
                                       __float2bfloat16_rn(acc[f].y * inv));
        op[2 * f + 1] = __nv_bfloat162(__float2bfloat16_rn(acc[f].z * inv),
                                       __float2bfloat16_rn(acc[f].w * inv));
    }
}

// ---------------- ln_sum: GEMM out + bias + residual, LN, dual fp32/bf16 output ----------------
__global__ __launch_bounds__(128) void ln_sum_kernel(
    const float* __restrict__ gin,
    const float* __restrict__ bias, const float* __restrict__ res,
    const float* __restrict__ g, const float* __restrict__ b,
    float* __restrict__ out, __nv_bfloat16* __restrict__ out_b)
{
    const int row = blockIdx.x;
    const int t = threadIdx.x;
    const size_t off = (size_t)row * DMODEL;

    float4 v = ((const float4*)(gin + off))[t];
    const float4 bi = ((const float4*)bias)[t];
    const float4 rr = ((const float4*)(res + off))[t];
    v.x += bi.x + rr.x; v.y += bi.y + rr.y;
    v.z += bi.z + rr.z; v.w += bi.w + rr.w;

    float s  = v.x + v.y + v.z + v.w;
    float ss = v.x * v.x + v.y * v.y + v.z * v.z + v.w * v.w;
#pragma unroll
    for (int o2 = 16; o2; o2 >>= 1) {
        s  += __shfl_xor_sync(0xffffffffu, s, o2);
        ss += __shfl_xor_sync(0xffffffffu, ss, o2);
    }
    __shared__ float red[8];
    const int wid = t >> 5;
    if ((t & 31) == 0) { red[wid] = s; red[4 + wid] = ss; }
    __syncthreads();
    s  = red[0] + red[1] + red[2] + red[3];
    ss = red[4] + red[5] + red[6] + red[7];

    const float mean = s * (1.f / DMODEL);
    const float var  = ss * (1.f / DMODEL) - mean * mean;
    const float rs = rsqrtf(var + LN_EPS);

    const float4 gg = ((const float4*)g)[t];
    const float4 bb = ((const float4*)b)[t];
    float4 o;
    o.x = (v.x - mean) * rs * gg.x + bb.x;
    o.y = (v.y - mean) * rs * gg.y + bb.y;
    o.z = (v.z - mean) * rs * gg.z + bb.z;
    o.w = (v.w - mean) * rs * gg.w + bb.w;
    ((float4*)(out + off))[t] = o;
    if (out_b) {
        __nv_bfloat162* d = (__nv_bfloat162*)(out_b + off);
        d[2 * t]     = __nv_bfloat162(__float2bfloat16_rn(o.x), __float2bfloat16_rn(o.y));
        d[2 * t + 1] = __nv_bfloat162(__float2bfloat16_rn(o.z), __float2bfloat16_rn(o.w));
    }
}

// ---------------- launch ----------------
extern "C" void kernel_launch(void* const* d_in, const int* in_sizes, int n_in,
                              void* d_out, int out_size)
{
    const float* x   = (const float*)d_in[0];
    const float* enc = (const float*)d_in[1];
    const float* sa_Wq = (const float*)d_in[2];
    const float* sa_Wk = (const float*)d_in[3];
    const float* sa_Wv = (const float*)d_in[4];
    const float* sa_Wo = (const float*)d_in[5];
    const float* sa_bq = (const float*)d_in[6];
    const float* sa_bk = (const float*)d_in[7];
    const float* sa_bv = (const float*)d_in[8];
    const float* sa_bo = (const float*)d_in[9];
    const float* ca_Wq = (const float*)d_in[10];
    const float* ca_Wk = (const float*)d_in[11];
    const float* ca_Wv = (const float*)d_in[12];
    const float* ca_Wo = (const float*)d_in[13];
    const float* ca_bq = (const float*)d_in[14];
    const float* ca_bk = (const float*)d_in[15];
    const float* ca_bv = (const float*)d_in[16];
    const float* ca_bo = (const float*)d_in[17];
    const float* ff_W1 = (const float*)d_in[18];
    const float* ff_W2 = (const float*)d_in[19];
    const float* ff_b1 = (const float*)d_in[20];
    const float* ff_b2 = (const float*)d_in[21];
    const float* ln1_g = (const float*)d_in[22];
    const float* ln1_b = (const float*)d_in[23];
    const float* ln2_g = (const float*)d_in[24];
    const float* ln2_b = (const float*)d_in[25];
    const float* ln3_g = (const float*)d_in[26];
    const float* ln3_b = (const float*)d_in[27];
    float* out = (float*)d_out;

    float *qkv, *kv, *qc, *part, *x1, *x2, *bsa, *bca;
    __nv_bfloat16 *wb, *xb, *encb, *x1b, *x2b, *attnb, *ffb;
    cudaGetSymbolAddress((void**)&qkv, g_qkv);
    cudaGetSymbolAddress((void**)&kv, g_kv);
    cudaGetSymbolAddress((void**)&qc, g_qc);
    cudaGetSymbolAddress((void**)&part, g_part);
    cudaGetSymbolAddress((void**)&x1, g_x1);
    cudaGetSymbolAddress((void**)&x2, g_x2);
    cudaGetSymbolAddress((void**)&bsa, g_bsa);
    cudaGetSymbolAddress((void**)&bca, g_bca);
    cudaGetSymbolAddress((void**)&wb, g_wb);
    cudaGetSymbolAddress((void**)&xb, g_xb);
    cudaGetSymbolAddress((void**)&encb, g_encb);
    cudaGetSymbolAddress((void**)&x1b, g_x1b);
    cudaGetSymbolAddress((void**)&x2b, g_x2b);
    cudaGetSymbolAddress((void**)&attnb, g_attnb);
    cudaGetSymbolAddress((void**)&ffb, g_ffb);

    const int PW = DMODEL * DMODEL;
    __nv_bfloat16* w_saWqkv = wb + 0 * PW;            // Wq|Wk|Wv contiguous
    __nv_bfloat16* w_saWo   = wb + 3 * PW;
    __nv_bfloat16* w_caWq   = wb + 4 * PW;
    __nv_bfloat16* w_caWkv  = wb + 5 * PW;            // Wk|Wv contiguous
    __nv_bfloat16* w_caWo   = wb + 7 * PW;
    __nv_bfloat16* w_ffW1   = wb + 8 * PW;
    __nv_bfloat16* w_ffW2   = wb + 8 * PW + FFDIM * DMODEL;

    CvtArgs ca;
    const float* srcs[NCVT] = { sa_Wq, sa_Wk, sa_Wv, sa_Wo, ca_Wq, ca_Wk, ca_Wv, ca_Wo,
                                ff_W1, ff_W2, x, enc,
                                sa_bq, sa_bk, sa_bv, ca_bk, ca_bv };
    void* dsts[NCVT] = { w_saWqkv, w_saWqkv + PW, w_saWqkv + 2 * PW, w_saWo,
                         w_caWq, w_caWkv, w_caWkv + PW, w_caWo,
                         w_ffW1, w_ffW2, xb, encb,
                         bsa, bsa + DMODEL, bsa + 2 * DMODEL, bca, bca + DMODEL };
    int ns[NCVT] = { PW, PW, PW, PW, PW, PW, PW, PW,
                     FFDIM * DMODEL, FFDIM * DMODEL, NTOK * DMODEL, NTOK * DMODEL,
                     DMODEL, DMODEL, DMODEL, DMODEL, DMODEL };
    int tob[NCVT] = { 1,1,1,1, 1,1,1,1, 1,1, 1,1, 0,0,0, 0,0 };
    for (int i = 0; i < NCVT; i++) {
        ca.src[i] = srcs[i]; ca.dst[i] = dsts[i]; ca.n4[i] = ns[i] / 4; ca.tobf[i] = tob[i];
    }

    cudaFuncSetAttribute(gemm_bf16_kernel,
                         cudaFuncAttributeMaxDynamicSharedMemorySize, GEMM_SMEM_BYTES);

    const dim3 gblk(256);
    const dim3 gQKV(3 * DMODEL / GBN, NTOK / GBM);   // (24, 32) = 768 blocks
    const dim3 gKV(2 * DMODEL / GBN, NTOK / GBM);    // (16, 32) = 512
    const dim3 gProj(DMODEL / GBN, NTOK / GBM);      // (8, 32)  = 256
    const dim3 gFF1(FFDIM / GBN, NTOK / GBM);        // (32, 32) = 1024
    const dim3 gAttn(S_LEN / AQ_PER_BLOCK, BATCH * NHEAD);

    cvt_kernel<<<dim3(128, NCVT), 256>>>(ca);

    // ---- self attention ----
    gemm_bf16_kernel<<<gQKV, gblk, GEMM_SMEM_BYTES>>>(xb, w_saWqkv, bsa, qkv, NTOK, 3 * DMODEL, DMODEL, 0);
    attn4_kernel<<<gAttn, 256>>>(qkv, 3 * DMODEL, qkv + DMODEL, qkv + 2 * DMODEL, 3 * DMODEL, attnb);
    gemm_bf16_kernel<<<gProj, gblk, GEMM_SMEM_BYTES>>>(attnb, w_saWo, nullptr, part, NTOK, DMODEL, DMODEL, 0);
    ln_sum_kernel<<<NTOK, 128>>>(part, sa_bo, x, ln1_g, ln1_b, x1, x1b);

    // ---- cross attention ----
    gemm_bf16_kernel<<<gKV, gblk, GEMM_SMEM_BYTES>>>(encb, w_caWkv, bca, kv, NTOK, 2 * DMODEL, DMODEL, 0);
    gemm_bf16_kernel<<<gProj, gblk, GEMM_SMEM_BYTES>>>(x1b, w_caWq, ca_bq, qc, NTOK, DMODEL, DMODEL, 0);
    attn4_kernel<<<gAttn, 256>>>(qc, DMODEL, kv, kv + DMODEL, 2 * DMODEL, attnb);
    gemm_bf16_kernel<<<gProj, gblk, GEMM_SMEM_BYTES>>>(attnb, w_caWo, nullptr, part, NTOK, DMODEL, DMODEL, 0);
    ln_sum_kernel<<<NTOK, 128>>>(part, ca_bo, x1, ln2_g, ln2_b, x2, x2b);

    // ---- feed forward ----
    gemm_bf16_kernel<<<gFF1, gblk, GEMM_SMEM_BYTES>>>(x2b, w_ffW1, ff_b1, (float*)ffb, NTOK, FFDIM, DMODEL, EF_RELU | EF_BF16OUT);
    gemm_bf16_kernel<<<gProj, gblk, GEMM_SMEM_BYTES>>>(ffb, w_ffW2, nullptr, part, NTOK, DMODEL, FFDIM, 0);
    ln_sum_kernel<<<NTOK, 128>>>(part, ff_b2, x2, ln3_g, ln3_b, out, nullptr);
}